// round 10
// baseline (speedup 1.0000x reference)
#include <cuda_runtime.h>
#include <cuda_bf16.h>

// ---------------- problem constants ----------------
#define NBLK   140
#define NTH    512
#define NWARPS (NBLK * 16)
#define LOG2E  1.4426950408889634f
#define TANH2L 2.8853900817779268f   // 2*log2(e)

// ---------------- device scratch (allocs forbidden) ----------------
__device__ __align__(128) float g_WUp[8192 * 1024];  // [p*32+b][h]
__device__ __align__(128) float g_WUq[8192 * 1024];  // [q*32+b][h]
__device__ __align__(128) float g_UG [8192 * 1024];  // [p*32+b][h]
__device__ __align__(128) float g_WpF[1024 * 512];
__device__ __align__(128) float g_WqF[1024 * 512];
__device__ __align__(128) float g_WgU[1024 * 512];
__device__ __align__(128) float g_WgC[1024 * 512];
__device__ __align__(128) float g_v  [32 * 1024];
__device__ __align__(128) float g_z1 [32 * 1024];
__device__ __align__(128) float g_gh [32 * 3072];
__device__ __align__(128) float g_s  [32 * 256];
__device__ __align__(128) float g_cu [32 * 512];
__device__ __align__(128) float g_ch [32 * 1024];
__device__ unsigned g_barcnt;

// ---------------- helpers ----------------
__device__ __forceinline__ float fexp2(float x) {
    float y; asm("ex2.approx.f32 %0, %1;" : "=f"(y) : "f"(x)); return y;
}
__device__ __forceinline__ float frcp(float x) {
    float y; asm("rcp.approx.f32 %0, %1;" : "=f"(y) : "f"(x)); return y;
}
// tanh(x) = 1 - 2/(1 + 2^(2x*log2e)); exact at +-inf, ~1e-6 rel err
__device__ __forceinline__ float tanh_fast(float x) {
    return fmaf(-2.0f, frcp(1.0f + fexp2(x * TANH2L)), 1.0f);
}
__device__ __forceinline__ float sigm_fast(float x) {
    return frcp(1.0f + fexp2(-x * LOG2E));
}
__device__ __forceinline__ float wsum(float v) {
    v += __shfl_xor_sync(0xffffffffu, v, 16);
    v += __shfl_xor_sync(0xffffffffu, v, 8);
    v += __shfl_xor_sync(0xffffffffu, v, 4);
    v += __shfl_xor_sync(0xffffffffu, v, 2);
    v += __shfl_xor_sync(0xffffffffu, v, 1);
    return v;
}
__device__ __forceinline__ float wmax(float v) {
    v = fmaxf(v, __shfl_xor_sync(0xffffffffu, v, 16));
    v = fmaxf(v, __shfl_xor_sync(0xffffffffu, v, 8));
    v = fmaxf(v, __shfl_xor_sync(0xffffffffu, v, 4));
    v = fmaxf(v, __shfl_xor_sync(0xffffffffu, v, 2));
    v = fmaxf(v, __shfl_xor_sync(0xffffffffu, v, 1));
    return v;
}
// grid-wide barrier: monotonically increasing counter, reset by init kernel
__device__ __forceinline__ void gsync(unsigned barno) {
    __syncthreads();
    if (threadIdx.x == 0) {
        __threadfence();
        atomicAdd(&g_barcnt, 1u);
        const unsigned tgt = barno * (unsigned)NBLK;
        unsigned v;
        do {
            asm volatile("ld.acquire.gpu.u32 %0, [%1];" : "=r"(v) : "l"(&g_barcnt));
        } while (v < tgt);
    }
    __syncthreads();
}

// ---------------- init ----------------
__global__ void init_kernel(const float* __restrict__ v0) {
    int i = blockIdx.x * blockDim.x + threadIdx.x;
    if (i == 0) g_barcnt = 0u;
    if (i < 32 * 1024) g_v[i] = v0[i];
}

// ---------------- weight folding ----------------
__global__ void fold_kernel(const float* __restrict__ Wp,
                            const float* __restrict__ Wq,
                            const float* __restrict__ Wg) {
    int idx = blockIdx.x * blockDim.x + threadIdx.x;
    if (idx >= 1024 * 512) return;
    int h = idx >> 9, i = idx & 511;
    g_WpF[idx] = Wp[h * 1024 + i] + Wp[h * 1024 + 512 + i];
    g_WqF[idx] = Wq[h * 1024 + i] + Wq[h * 1024 + 512 + i];
    const float* wgr = Wg + (size_t)(1024 + h) * 2048;
    g_WgU[idx] = wgr[i]        + wgr[512 + i];
    g_WgC[idx] = wgr[1024 + i] + wgr[1536 + i];
}

// ---------------- precompute GEMMs: O[r,h] = sum_k A[r,k]*W[h,k] ----------------
// M=8192, N=1024, K=512.  z=0: WUq = uq*WqF ; z=1: WUp = up*WpF ; z=2: UG = up*WgU
__global__ __launch_bounds__(256) void gemm_kernel(const float* __restrict__ up,
                                                   const float* __restrict__ uq) {
    __shared__ float As[16][68];
    __shared__ float Ws[16][68];
    const int z = blockIdx.z;
    const float* A = (z == 0) ? uq : up;
    const float* W = (z == 0) ? g_WqF : ((z == 1) ? g_WpF : g_WgU);
    float*       O = (z == 0) ? g_WUq : ((z == 1) ? g_WUp : g_UG);
    const int m0 = blockIdx.y * 64;
    const int n0 = blockIdx.x * 64;
    const int tid = threadIdx.x;
    const int tr = tid >> 4;          // 0..15
    const int tc = tid & 15;          // 0..15
    const int lr = tid >> 2;          // 0..63
    const int lk = (tid & 3) * 4;     // 0,4,8,12

    float acc[4][4];
#pragma unroll
    for (int i = 0; i < 4; i++)
#pragma unroll
        for (int j = 0; j < 4; j++) acc[i][j] = 0.f;

    for (int kt = 0; kt < 512; kt += 16) {
        float4 av = *(const float4*)&A[(size_t)(m0 + lr) * 512 + kt + lk];
        float4 wv = *(const float4*)&W[(size_t)(n0 + lr) * 512 + kt + lk];
        __syncthreads();
        As[lk + 0][lr] = av.x; As[lk + 1][lr] = av.y; As[lk + 2][lr] = av.z; As[lk + 3][lr] = av.w;
        Ws[lk + 0][lr] = wv.x; Ws[lk + 1][lr] = wv.y; Ws[lk + 2][lr] = wv.z; Ws[lk + 3][lr] = wv.w;
        __syncthreads();
#pragma unroll
        for (int kk = 0; kk < 16; kk++) {
            float4 a4 = *(const float4*)&As[kk][tr * 4];
            float4 w4 = *(const float4*)&Ws[kk][tc * 4];
            float a[4] = {a4.x, a4.y, a4.z, a4.w};
            float w[4] = {w4.x, w4.y, w4.z, w4.w};
#pragma unroll
            for (int i = 0; i < 4; i++)
#pragma unroll
                for (int j = 0; j < 4; j++) acc[i][j] = fmaf(a[i], w[j], acc[i][j]);
        }
    }
#pragma unroll
    for (int i = 0; i < 4; i++) {
        float4 o = make_float4(acc[i][0], acc[i][1], acc[i][2], acc[i][3]);
        *(float4*)&O[(size_t)(m0 + tr * 4 + i) * 1024 + n0 + tc * 4] = o;
    }
}

// ---------------- persistent recurrent loop ----------------
__global__ __launch_bounds__(NTH, 1) void loop_kernel(
    const float* __restrict__ uq,
    const float* __restrict__ Vvec,
    const float* __restrict__ Wv,
    const float* __restrict__ W_hh,
    const float* __restrict__ b_hh,
    const float* __restrict__ W_ih,
    const float* __restrict__ b_ih,
    float* __restrict__ out)
{
    extern __shared__ float sh[];   // 33792 floats = 132 KB
    const int tid  = threadIdx.x;
    const int lane = tid & 31;
    const int warp = tid >> 5;
    const int wgid = blockIdx.x * (NTH / 32) + warp;
    unsigned barno = 0;

    for (int p = 0; p < 256; ++p) {
        // ===== Phase A: z1 = v@Wv^T ; gh = v@W_hh^T + b_hh  (4096 rows x 32 b, K=1024)
        for (int idx = tid; idx < 32768; idx += NTH) {
            int b = idx >> 10, k = idx & 1023;
            sh[k * 33 + b] = __ldcg(&g_v[idx]);
        }
        __syncthreads();
        {
            int r0 = wgid * 2;
            if (r0 < 4096) {
                int r1 = r0 + 1;
                const float* W0 = (r0 < 1024) ? (Wv + (size_t)r0 * 1024)
                                              : (W_hh + (size_t)(r0 - 1024) * 1024);
                const float* W1 = (r1 < 1024) ? (Wv + (size_t)r1 * 1024)
                                              : (W_hh + (size_t)(r1 - 1024) * 1024);
                float a0 = (r0 < 1024) ? 0.f : b_hh[r0 - 1024];
                float a1 = (r1 < 1024) ? 0.f : b_hh[r1 - 1024];
#pragma unroll 4
                for (int k = 0; k < 1024; k += 4) {
                    float4 w0 = *(const float4*)(W0 + k);
                    float4 w1 = *(const float4*)(W1 + k);
                    float s0 = sh[(k + 0) * 33 + lane];
                    float s1 = sh[(k + 1) * 33 + lane];
                    float s2 = sh[(k + 2) * 33 + lane];
                    float s3 = sh[(k + 3) * 33 + lane];
                    a0 = fmaf(w0.x, s0, a0); a0 = fmaf(w0.y, s1, a0);
                    a0 = fmaf(w0.z, s2, a0); a0 = fmaf(w0.w, s3, a0);
                    a1 = fmaf(w1.x, s0, a1); a1 = fmaf(w1.y, s1, a1);
                    a1 = fmaf(w1.z, s2, a1); a1 = fmaf(w1.w, s3, a1);
                }
                if (r0 < 1024) g_z1[lane * 1024 + r0] = a0;
                else           g_gh[lane * 3072 + r0 - 1024] = a0;
                if (r1 < 1024) g_z1[lane * 1024 + r1] = a1;
                else           g_gh[lane * 3072 + r1 - 1024] = a1;
            }
        }
        gsync(++barno);

        // ===== Phase B: s[b,q] = sum_h tanh(WUq[q,b,h] + (WUp[p,b,h]+z1[b,h])) * Vvec[b,h]
        for (int idx = tid; idx < 32768; idx += NTH)
            sh[idx] = __ldg(&g_WUp[(size_t)p * 32768 + idx]) + __ldcg(&g_z1[idx]);
        __syncthreads();
        for (int pair = wgid; pair < 8192; pair += NWARPS) {
            int b = pair & 31;
            const float* wuq = g_WUq + (size_t)pair * 1024;
            const float* vv  = Vvec + b * 1024;
            const float* zw  = sh + b * 1024;
            float part = 0.f;
#pragma unroll 2
            for (int h = lane * 4; h < 1024; h += 128) {
                float4 wq4 = __ldg((const float4*)(wuq + h));
                float4 vv4 = __ldg((const float4*)(vv + h));
                float4 zz  = *(const float4*)(zw + h);
                part = fmaf(tanh_fast(wq4.x + zz.x), vv4.x, part);
                part = fmaf(tanh_fast(wq4.y + zz.y), vv4.y, part);
                part = fmaf(tanh_fast(wq4.z + zz.z), vv4.z, part);
                part = fmaf(tanh_fast(wq4.w + zz.w), vv4.w, part);
            }
            part = wsum(part);
            if (lane == 0) g_s[b * 256 + (pair >> 5)] = part;
        }
        gsync(++barno);

        // ===== Phase C2: per-warp softmax recompute + cu[b,j] = sum_q a[b,q]*uq[q,b,j]
        if (wgid < 128) {
            int b = wgid >> 2, jb = (wgid & 3) * 128;
            float sv[8]; float mx = -3.4e38f;
#pragma unroll
            for (int i = 0; i < 8; i++) {
                sv[i] = __ldcg(&g_s[b * 256 + i * 32 + lane]);
                mx = fmaxf(mx, sv[i]);
            }
            mx = wmax(mx);
            float zsum = 0.f;
#pragma unroll
            for (int i = 0; i < 8; i++) { sv[i] = fexp2((sv[i] - mx) * LOG2E); zsum += sv[i]; }
            zsum = wsum(zsum);
            float inv = frcp(zsum);
#pragma unroll
            for (int i = 0; i < 8; i++) sv[i] *= inv;
            float4 acc = make_float4(0.f, 0.f, 0.f, 0.f);
            for (int q = 0; q < 256; ++q) {
                float aq = __shfl_sync(0xffffffffu, sv[q >> 5], q & 31);
                float4 u = __ldg((const float4*)&uq[(size_t)(q * 32 + b) * 512 + jb + lane * 4]);
                acc.x = fmaf(aq, u.x, acc.x); acc.y = fmaf(aq, u.y, acc.y);
                acc.z = fmaf(aq, u.z, acc.z); acc.w = fmaf(aq, u.w, acc.w);
            }
            *(float4*)&g_cu[b * 512 + jb + lane * 4] = acc;
        }
        gsync(++barno);

        // ===== Phase C3: c_[b,h] = sigmoid(UG[p,b,h] + cu@WgC^T) * cu[b, h&511]
        for (int idx = tid; idx < 16384; idx += NTH) {
            int b = idx >> 9, k = idx & 511;
            sh[k * 33 + b] = __ldcg(&g_cu[idx]);
        }
        __syncthreads();
        if (wgid < 1024) {
            int h = wgid;
            const float* wg = g_WgC + (size_t)h * 512;
            float acc = __ldg(&g_UG[(size_t)(p * 32 + lane) * 1024 + h]);
#pragma unroll 4
            for (int k = 0; k < 512; k += 4) {
                float4 w4 = *(const float4*)(wg + k);
                acc = fmaf(w4.x, sh[(k + 0) * 33 + lane], acc);
                acc = fmaf(w4.y, sh[(k + 1) * 33 + lane], acc);
                acc = fmaf(w4.z, sh[(k + 2) * 33 + lane], acc);
                acc = fmaf(w4.w, sh[(k + 3) * 33 + lane], acc);
            }
            float cval = sh[(h & 511) * 33 + lane];
            g_ch[lane * 1024 + h] = sigm_fast(acc) * cval;
        }
        gsync(++barno);

        // ===== Phase D: gi = c_@W_ih^T + b_ih ; GRU combine ; emit v_new
        for (int idx = tid; idx < 32768; idx += NTH) {
            int b = idx >> 10, k = idx & 1023;
            sh[k * 33 + b] = __ldcg(&g_ch[idx]);
        }
        __syncthreads();
        if (wgid < 1024) {
            int h = wgid;
            const float* Wr = W_ih + (size_t)h * 1024;
            const float* Wz = W_ih + (size_t)(1024 + h) * 1024;
            const float* Wn = W_ih + (size_t)(2048 + h) * 1024;
            float ar = b_ih[h], az = b_ih[1024 + h], an = b_ih[2048 + h];
#pragma unroll 4
            for (int k = 0; k < 1024; k += 4) {
                float4 wr = *(const float4*)(Wr + k);
                float4 wz = *(const float4*)(Wz + k);
                float4 wn = *(const float4*)(Wn + k);
                float s0 = sh[(k + 0) * 33 + lane];
                float s1 = sh[(k + 1) * 33 + lane];
                float s2 = sh[(k + 2) * 33 + lane];
                float s3 = sh[(k + 3) * 33 + lane];
                ar = fmaf(wr.x, s0, ar); ar = fmaf(wr.y, s1, ar);
                ar = fmaf(wr.z, s2, ar); ar = fmaf(wr.w, s3, ar);
                az = fmaf(wz.x, s0, az); az = fmaf(wz.y, s1, az);
                az = fmaf(wz.z, s2, az); az = fmaf(wz.w, s3, az);
                an = fmaf(wn.x, s0, an); an = fmaf(wn.y, s1, an);
                an = fmaf(wn.z, s2, an); an = fmaf(wn.w, s3, an);
            }
            float ghr = __ldcg(&g_gh[lane * 3072 + h]);
            float ghz = __ldcg(&g_gh[lane * 3072 + 1024 + h]);
            float ghn = __ldcg(&g_gh[lane * 3072 + 2048 + h]);
            float vold = __ldcg(&g_v[lane * 1024 + h]);
            float r  = sigm_fast(ar + ghr);
            float zg = sigm_fast(az + ghz);
            float n  = tanh_fast(fmaf(r, ghn, an));
            float vn = fmaf(zg, vold - n, n);
            g_v[lane * 1024 + h] = vn;
            out[(size_t)(p * 32 + lane) * 1024 + h] = vn;
        }
        gsync(++barno);
    }
}

// ---------------- launch ----------------
extern "C" void kernel_launch(void* const* d_in, const int* in_sizes, int n_in,
                              void* d_out, int out_size) {
    const float* up   = (const float*)d_in[0];
    const float* uq   = (const float*)d_in[1];
    const float* v0   = (const float*)d_in[2];
    const float* Vvec = (const float*)d_in[3];
    const float* Wp   = (const float*)d_in[4];
    const float* Wq   = (const float*)d_in[5];
    const float* Wv   = (const float*)d_in[6];
    const float* Wg   = (const float*)d_in[7];
    const float* W_ih = (const float*)d_in[8];
    const float* W_hh = (const float*)d_in[9];
    const float* b_ih = (const float*)d_in[10];
    const float* b_hh = (const float*)d_in[11];
    float* out = (float*)d_out;

    cudaFuncSetAttribute(loop_kernel, cudaFuncAttributeMaxDynamicSharedMemorySize,
                         33792 * (int)sizeof(float));

    init_kernel<<<64, 512>>>(v0);
    fold_kernel<<<2048, 256>>>(Wp, Wq, Wg);
    dim3 gg(16, 128, 3);
    gemm_kernel<<<gg, 256>>>(up, uq);
    loop_kernel<<<NBLK, NTH, 33792 * sizeof(float)>>>(uq, Vvec, Wv, W_hh, b_hh,
                                                      W_ih, b_ih, out);
}

// round 11
// speedup vs baseline: 1.0033x; 1.0033x over previous
#include <cuda_runtime.h>
#include <cuda_bf16.h>

// ---------------- problem constants ----------------
#define NBLK   140
#define NTH    512
#define NWARPS (NBLK * 16)
#define LOG2E  1.4426950408889634f
#define TANH2L 2.8853900817779268f   // 2*log2(e)

typedef unsigned long long ull;

// ---------------- device scratch (allocs forbidden) ----------------
__device__ __align__(128) float g_WUp[8192 * 1024];  // [p*32+b][h]
__device__ __align__(128) float g_WUq[8192 * 1024];  // [q*32+b][h]
__device__ __align__(128) float g_UG [8192 * 1024];  // [p*32+b][h]
__device__ __align__(128) float g_WpF[1024 * 512];
__device__ __align__(128) float g_WqF[1024 * 512];
__device__ __align__(128) float g_WgU[1024 * 512];
__device__ __align__(128) float g_WgC[1024 * 512];
__device__ __align__(128) float g_v  [32 * 1024];
__device__ __align__(128) float g_z1h[2 * 32 * 1024];   // k-half partials of v@Wv^T
__device__ __align__(128) float g_ghh[2 * 32 * 3072];   // k-half partials of v@W_hh^T
__device__ __align__(128) float g_s  [32 * 256];
__device__ __align__(128) float g_cuh[2 * 32 * 512];    // q-half partials of context
__device__ __align__(128) float g_ch [32 * 1024];
__device__ unsigned g_barcnt;

// ---------------- scalar helpers ----------------
__device__ __forceinline__ float fexp2(float x) {
    float y; asm("ex2.approx.f32 %0, %1;" : "=f"(y) : "f"(x)); return y;
}
__device__ __forceinline__ float frcp(float x) {
    float y; asm("rcp.approx.f32 %0, %1;" : "=f"(y) : "f"(x)); return y;
}
// tanh(x) = 1 - 2/(1 + 2^(2x*log2e)); exact at +-inf, ~1e-6 rel err
__device__ __forceinline__ float tanh_fast(float x) {
    return fmaf(-2.0f, frcp(1.0f + fexp2(x * TANH2L)), 1.0f);
}
__device__ __forceinline__ float sigm_fast(float x) {
    return frcp(1.0f + fexp2(-x * LOG2E));
}
__device__ __forceinline__ float wsum(float v) {
    v += __shfl_xor_sync(0xffffffffu, v, 16);
    v += __shfl_xor_sync(0xffffffffu, v, 8);
    v += __shfl_xor_sync(0xffffffffu, v, 4);
    v += __shfl_xor_sync(0xffffffffu, v, 2);
    v += __shfl_xor_sync(0xffffffffu, v, 1);
    return v;
}
__device__ __forceinline__ float wmax(float v) {
    v = fmaxf(v, __shfl_xor_sync(0xffffffffu, v, 16));
    v = fmaxf(v, __shfl_xor_sync(0xffffffffu, v, 8));
    v = fmaxf(v, __shfl_xor_sync(0xffffffffu, v, 4));
    v = fmaxf(v, __shfl_xor_sync(0xffffffffu, v, 2));
    v = fmaxf(v, __shfl_xor_sync(0xffffffffu, v, 1));
    return v;
}

// ---------------- packed f32x2 helpers (Blackwell) ----------------
__device__ __forceinline__ ull ffma2(ull a, ull b, ull c) {
    ull d; asm("fma.rn.f32x2 %0, %1, %2, %3;" : "=l"(d) : "l"(a), "l"(b), "l"(c));
    return d;
}
__device__ __forceinline__ float2 upk(ull v) {
    float2 r; asm("mov.b64 {%0, %1}, %2;" : "=f"(r.x), "=f"(r.y) : "l"(v));
    return r;
}
__device__ __forceinline__ float sum2(ull a, ull b) {
    float2 fa = upk(a), fb = upk(b);
    return (fa.x + fb.x) + (fa.y + fb.y);
}

// grid-wide barrier: monotonically increasing counter, reset by init kernel
__device__ __forceinline__ void gsync(unsigned barno) {
    __syncthreads();
    if (threadIdx.x == 0) {
        __threadfence();
        atomicAdd(&g_barcnt, 1u);
        const unsigned tgt = barno * (unsigned)NBLK;
        unsigned v;
        do {
            asm volatile("ld.acquire.gpu.u32 %0, [%1];" : "=r"(v) : "l"(&g_barcnt));
        } while (v < tgt);
    }
    __syncthreads();
}

// ---------------- init ----------------
__global__ void init_kernel(const float* __restrict__ v0) {
    int i = blockIdx.x * blockDim.x + threadIdx.x;
    if (i == 0) g_barcnt = 0u;
    if (i < 32 * 1024) g_v[i] = v0[i];
}

// ---------------- weight folding ----------------
__global__ void fold_kernel(const float* __restrict__ Wp,
                            const float* __restrict__ Wq,
                            const float* __restrict__ Wg) {
    int idx = blockIdx.x * blockDim.x + threadIdx.x;
    if (idx >= 1024 * 512) return;
    int h = idx >> 9, i = idx & 511;
    g_WpF[idx] = Wp[h * 1024 + i] + Wp[h * 1024 + 512 + i];
    g_WqF[idx] = Wq[h * 1024 + i] + Wq[h * 1024 + 512 + i];
    const float* wgr = Wg + (size_t)(1024 + h) * 2048;
    g_WgU[idx] = wgr[i]        + wgr[512 + i];
    g_WgC[idx] = wgr[1024 + i] + wgr[1536 + i];
}

// ---------------- precompute GEMMs: O[r,h] = sum_k A[r,k]*W[h,k] ----------------
// M=8192, N=1024, K=512.  z=0: WUq = uq*WqF ; z=1: WUp = up*WpF ; z=2: UG = up*WgU
__global__ __launch_bounds__(256) void gemm_kernel(const float* __restrict__ up,
                                                   const float* __restrict__ uq) {
    __shared__ float As[16][68];
    __shared__ float Ws[16][68];
    const int z = blockIdx.z;
    const float* A = (z == 0) ? uq : up;
    const float* W = (z == 0) ? g_WqF : ((z == 1) ? g_WpF : g_WgU);
    float*       O = (z == 0) ? g_WUq : ((z == 1) ? g_WUp : g_UG);
    const int m0 = blockIdx.y * 64;
    const int n0 = blockIdx.x * 64;
    const int tid = threadIdx.x;
    const int tr = tid >> 4;          // 0..15
    const int tc = tid & 15;          // 0..15
    const int lr = tid >> 2;          // 0..63
    const int lk = (tid & 3) * 4;     // 0,4,8,12

    float acc[4][4];
#pragma unroll
    for (int i = 0; i < 4; i++)
#pragma unroll
        for (int j = 0; j < 4; j++) acc[i][j] = 0.f;

    for (int kt = 0; kt < 512; kt += 16) {
        float4 av = *(const float4*)&A[(size_t)(m0 + lr) * 512 + kt + lk];
        float4 wv = *(const float4*)&W[(size_t)(n0 + lr) * 512 + kt + lk];
        __syncthreads();
        As[lk + 0][lr] = av.x; As[lk + 1][lr] = av.y; As[lk + 2][lr] = av.z; As[lk + 3][lr] = av.w;
        Ws[lk + 0][lr] = wv.x; Ws[lk + 1][lr] = wv.y; Ws[lk + 2][lr] = wv.z; Ws[lk + 3][lr] = wv.w;
        __syncthreads();
#pragma unroll
        for (int kk = 0; kk < 16; kk++) {
            float4 a4 = *(const float4*)&As[kk][tr * 4];
            float4 w4 = *(const float4*)&Ws[kk][tc * 4];
            float a[4] = {a4.x, a4.y, a4.z, a4.w};
            float w[4] = {w4.x, w4.y, w4.z, w4.w};
#pragma unroll
            for (int i = 0; i < 4; i++)
#pragma unroll
                for (int j = 0; j < 4; j++) acc[i][j] = fmaf(a[i], w[j], acc[i][j]);
        }
    }
#pragma unroll
    for (int i = 0; i < 4; i++) {
        float4 o = make_float4(acc[i][0], acc[i][1], acc[i][2], acc[i][3]);
        *(float4*)&O[(size_t)(m0 + tr * 4 + i) * 1024 + n0 + tc * 4] = o;
    }
}

// ---------------- persistent recurrent loop ----------------
// smem: 16896 x 8B = 135168 bytes.  Layouts by phase:
//   A/C3/D staging: packed float2 pairs   [k2 * 33 + b]
//   B staging:      flat float            [b * 1024 + h]
__global__ __launch_bounds__(NTH, 1) void loop_kernel(
    const float* __restrict__ uq,
    const float* __restrict__ Vvec,
    const float* __restrict__ Wv,
    const float* __restrict__ W_hh,
    const float* __restrict__ b_hh,
    const float* __restrict__ W_ih,
    const float* __restrict__ b_ih,
    float* __restrict__ out)
{
    extern __shared__ __align__(16) ull sh64[];
    float*  shf = (float*)sh64;
    float2* sh2 = (float2*)sh64;
    const int tid  = threadIdx.x;
    const int lane = tid & 31;
    const int warp = tid >> 5;
    const int wgid = blockIdx.x * 16 + warp;
    unsigned barno = 0;

    for (int p = 0; p < 256; ++p) {
        // ===== Phase A: z1 = v@Wv^T ; gh = v@W_hh^T  (4096 rows, K=1024, k-half split)
        {
            const float2* v2 = (const float2*)g_v;
            for (int idx2 = tid; idx2 < 16384; idx2 += NTH) {
                int b = idx2 >> 9, k2 = idx2 & 511;
                sh2[k2 * 33 + b] = __ldcg(&v2[idx2]);
            }
        }
        __syncthreads();
        {
            int t = blockIdx.x * 15 + warp;     // 2048 tasks: (4-row group, k-half)
            if (warp < 15 && t < 2048) {
                int rg = t >> 1, kh = t & 1;
                int rbase = rg << 2;
                const float* WB = (rbase < 1024)
                    ? (Wv + (size_t)rbase * 1024)
                    : (W_hh + (size_t)(rbase - 1024) * 1024);
                ull aA0 = 0, aA1 = 0, aA2 = 0, aA3 = 0;
                ull aB0 = 0, aB1 = 0, aB2 = 0, aB3 = 0;
                const int k20 = kh * 256;
#pragma unroll 2
                for (int k2 = k20; k2 < k20 + 256; k2 += 2) {
                    ull s01 = sh64[k2 * 33 + lane];
                    ull s23 = sh64[(k2 + 1) * 33 + lane];
                    ulonglong2 w0 = *(const ulonglong2*)(WB + 0 * 1024 + k2 * 2);
                    ulonglong2 w1 = *(const ulonglong2*)(WB + 1 * 1024 + k2 * 2);
                    ulonglong2 w2 = *(const ulonglong2*)(WB + 2 * 1024 + k2 * 2);
                    ulonglong2 w3 = *(const ulonglong2*)(WB + 3 * 1024 + k2 * 2);
                    aA0 = ffma2(w0.x, s01, aA0); aB0 = ffma2(w0.y, s23, aB0);
                    aA1 = ffma2(w1.x, s01, aA1); aB1 = ffma2(w1.y, s23, aB1);
                    aA2 = ffma2(w2.x, s01, aA2); aB2 = ffma2(w2.y, s23, aB2);
                    aA3 = ffma2(w3.x, s01, aA3); aB3 = ffma2(w3.y, s23, aB3);
                }
                float v0r = sum2(aA0, aB0), v1r = sum2(aA1, aB1);
                float v2r = sum2(aA2, aB2), v3r = sum2(aA3, aB3);
                if (rbase < 1024) {
                    float* dst = g_z1h + kh * 32768 + lane * 1024 + rbase;
                    dst[0] = v0r; dst[1] = v1r; dst[2] = v2r; dst[3] = v3r;
                } else {
                    float* dst = g_ghh + kh * 98304 + lane * 3072 + (rbase - 1024);
                    dst[0] = v0r; dst[1] = v1r; dst[2] = v2r; dst[3] = v3r;
                }
            }
        }
        gsync(++barno);

        // ===== Phase B: s[b,q] = sum_h tanh(WUq[q,b,h] + (WUp[p,b,h]+z1[b,h])) * Vvec[b,h]
        for (int idx = tid; idx < 32768; idx += NTH)
            shf[idx] = __ldg(&g_WUp[(size_t)p * 32768 + idx])
                     + __ldcg(&g_z1h[idx]) + __ldcg(&g_z1h[32768 + idx]);
        __syncthreads();
        for (int pair = wgid; pair < 8192; pair += NWARPS) {
            int b = pair & 31;
            const float* wuq = g_WUq + (size_t)pair * 1024;
            const float* vv  = Vvec + b * 1024;
            const float* zw  = shf + b * 1024;
            float part = 0.f;
#pragma unroll 2
            for (int h = lane * 4; h < 1024; h += 128) {
                float4 wq4 = __ldg((const float4*)(wuq + h));
                float4 vv4 = __ldg((const float4*)(vv + h));
                float4 zz  = *(const float4*)(zw + h);
                part = fmaf(tanh_fast(wq4.x + zz.x), vv4.x, part);
                part = fmaf(tanh_fast(wq4.y + zz.y), vv4.y, part);
                part = fmaf(tanh_fast(wq4.z + zz.z), vv4.z, part);
                part = fmaf(tanh_fast(wq4.w + zz.w), vv4.w, part);
            }
            part = wsum(part);
            if (lane == 0) g_s[b * 256 + (pair >> 5)] = part;
        }
        gsync(++barno);

        // ===== Phase C2: softmax (recomputed per warp) + partial context over q-half
        {
            int t = blockIdx.x * 2 + warp;      // 256 tasks: (b, 128-col block, q-half)
            if (warp < 2 && t < 256) {
                int b = t >> 3, r3 = t & 7;
                int jb = ((r3 >> 1) & 3) * 128;
                int qh = r3 & 1;
                float sv[8]; float mx = -3.4e38f;
#pragma unroll
                for (int i = 0; i < 8; i++) {
                    sv[i] = __ldcg(&g_s[b * 256 + i * 32 + lane]);
                    mx = fmaxf(mx, sv[i]);
                }
                mx = wmax(mx);
                float zsum = 0.f;
#pragma unroll
                for (int i = 0; i < 8; i++) { sv[i] = fexp2((sv[i] - mx) * LOG2E); zsum += sv[i]; }
                zsum = wsum(zsum);
                float inv = frcp(zsum);
#pragma unroll
                for (int i = 0; i < 8; i++) sv[i] *= inv;
                float4 acc = make_float4(0.f, 0.f, 0.f, 0.f);
                const int q0 = qh * 128;
#pragma unroll 4
                for (int q = q0; q < q0 + 128; ++q) {
                    float aq = __shfl_sync(0xffffffffu, sv[q >> 5], q & 31);
                    float4 u = __ldg((const float4*)&uq[(size_t)(q * 32 + b) * 512 + jb + lane * 4]);
                    acc.x = fmaf(aq, u.x, acc.x); acc.y = fmaf(aq, u.y, acc.y);
                    acc.z = fmaf(aq, u.z, acc.z); acc.w = fmaf(aq, u.w, acc.w);
                }
                *(float4*)&g_cuh[qh * 16384 + b * 512 + jb + lane * 4] = acc;
            }
        }
        gsync(++barno);

        // ===== Phase C3: c_[b,h] = sigmoid(UG[p,b,h] + cu@WgC^T) * cu[b, h&511]
        {
            const float2* cu2 = (const float2*)g_cuh;
            for (int idx2 = tid; idx2 < 8192; idx2 += NTH) {
                int b = idx2 >> 8, k2 = idx2 & 255;
                float2 x = __ldcg(&cu2[idx2]);
                float2 y = __ldcg(&cu2[8192 + idx2]);
                float2 s; s.x = x.x + y.x; s.y = x.y + y.y;
                sh2[k2 * 33 + b] = s;
            }
        }
        __syncthreads();
        {
            int h = blockIdx.x * 8 + warp;       // 1024 tasks, 8 per block
            if (warp < 8 && h < 1024) {
                const float* wg = g_WgC + (size_t)h * 512;
                ull aA = 0, aB = 0;
#pragma unroll 2
                for (int k2 = 0; k2 < 256; k2 += 2) {
                    ull s01 = sh64[k2 * 33 + lane];
                    ull s23 = sh64[(k2 + 1) * 33 + lane];
                    ulonglong2 w = *(const ulonglong2*)(wg + k2 * 2);
                    aA = ffma2(w.x, s01, aA);
                    aB = ffma2(w.y, s23, aB);
                }
                float acc = sum2(aA, aB)
                          + __ldg(&g_UG[(size_t)(p * 32 + lane) * 1024 + h]);
                int hc = h & 511;
                float2 cv2 = sh2[(hc >> 1) * 33 + lane];
                float cval = (h & 1) ? cv2.y : cv2.x;
                g_ch[lane * 1024 + h] = sigm_fast(acc) * cval;
            }
        }
        gsync(++barno);

        // ===== Phase D: gi = c_@W_ih^T + b_ih ; GRU combine ; emit v_new
        {
            const float2* ch2 = (const float2*)g_ch;
            for (int idx2 = tid; idx2 < 16384; idx2 += NTH) {
                int b = idx2 >> 9, k2 = idx2 & 511;
                sh2[k2 * 33 + b] = __ldcg(&ch2[idx2]);
            }
        }
        __syncthreads();
        {
            int h = blockIdx.x * 8 + warp;       // 1024 tasks, 8 per block
            if (warp < 8 && h < 1024) {
                const float* W0 = W_ih + (size_t)h * 1024;
                const float* W1 = W_ih + (size_t)(1024 + h) * 1024;
                const float* W2 = W_ih + (size_t)(2048 + h) * 1024;
                ull aA0 = 0, aA1 = 0, aA2 = 0;
                ull aB0 = 0, aB1 = 0, aB2 = 0;
#pragma unroll 2
                for (int k2 = 0; k2 < 512; k2 += 2) {
                    ull s01 = sh64[k2 * 33 + lane];
                    ull s23 = sh64[(k2 + 1) * 33 + lane];
                    ulonglong2 w0 = *(const ulonglong2*)(W0 + k2 * 2);
                    ulonglong2 w1 = *(const ulonglong2*)(W1 + k2 * 2);
                    ulonglong2 w2 = *(const ulonglong2*)(W2 + k2 * 2);
                    aA0 = ffma2(w0.x, s01, aA0); aB0 = ffma2(w0.y, s23, aB0);
                    aA1 = ffma2(w1.x, s01, aA1); aB1 = ffma2(w1.y, s23, aB1);
                    aA2 = ffma2(w2.x, s01, aA2); aB2 = ffma2(w2.y, s23, aB2);
                }
                float ar = sum2(aA0, aB0) + __ldg(&b_ih[h]);
                float az = sum2(aA1, aB1) + __ldg(&b_ih[1024 + h]);
                float an = sum2(aA2, aB2) + __ldg(&b_ih[2048 + h]);
                float ghr = __ldcg(&g_ghh[lane * 3072 + h])
                          + __ldcg(&g_ghh[98304 + lane * 3072 + h]) + __ldg(&b_hh[h]);
                float ghz = __ldcg(&g_ghh[lane * 3072 + 1024 + h])
                          + __ldcg(&g_ghh[98304 + lane * 3072 + 1024 + h]) + __ldg(&b_hh[1024 + h]);
                float ghn = __ldcg(&g_ghh[lane * 3072 + 2048 + h])
                          + __ldcg(&g_ghh[98304 + lane * 3072 + 2048 + h]) + __ldg(&b_hh[2048 + h]);
                float vold = __ldcg(&g_v[lane * 1024 + h]);
                float r  = sigm_fast(ar + ghr);
                float zg = sigm_fast(az + ghz);
                float n  = tanh_fast(fmaf(r, ghn, an));
                float vn = fmaf(zg, vold - n, n);
                g_v[lane * 1024 + h] = vn;
                out[(size_t)(p * 32 + lane) * 1024 + h] = vn;
            }
        }
        gsync(++barno);
    }
}

// ---------------- launch ----------------
extern "C" void kernel_launch(void* const* d_in, const int* in_sizes, int n_in,
                              void* d_out, int out_size) {
    const float* up   = (const float*)d_in[0];
    const float* uq   = (const float*)d_in[1];
    const float* v0   = (const float*)d_in[2];
    const float* Vvec = (const float*)d_in[3];
    const float* Wp   = (const float*)d_in[4];
    const float* Wq   = (const float*)d_in[5];
    const float* Wv   = (const float*)d_in[6];
    const float* Wg   = (const float*)d_in[7];
    const float* W_ih = (const float*)d_in[8];
    const float* W_hh = (const float*)d_in[9];
    const float* b_ih = (const float*)d_in[10];
    const float* b_hh = (const float*)d_in[11];
    float* out = (float*)d_out;

    const int smem_bytes = 16896 * (int)sizeof(ull);   // 135168
    cudaFuncSetAttribute(loop_kernel, cudaFuncAttributeMaxDynamicSharedMemorySize,
                         smem_bytes);

    init_kernel<<<64, 512>>>(v0);
    fold_kernel<<<2048, 256>>>(Wp, Wq, Wg);
    dim3 gg(16, 128, 3);
    gemm_kernel<<<gg, 256>>>(up, uq);
    loop_kernel<<<NBLK, NTH, smem_bytes>>>(uq, Vvec, Wv, W_hh, b_hh,
                                           W_ih, b_ih, out);
}

// round 13
// speedup vs baseline: 1.2898x; 1.2855x over previous
#include <cuda_runtime.h>
#include <cuda_bf16.h>

// ---------------- problem constants ----------------
#define NBLK   140
#define NTH    512
#define LOG2E  1.4426950408889634f
#define TANH2L 2.8853900817779268f   // 2*log2(e)

typedef unsigned long long ull;

// ---------------- device scratch (allocs forbidden) ----------------
__device__ __align__(128) float g_WUp[8192 * 1024];  // [p*32+b][h]
__device__ __align__(128) float g_WUq[8192 * 1024];  // [q*32+b][h]
__device__ __align__(128) float g_UG [8192 * 1024];  // [p*32+b][h]
__device__ __align__(128) float g_WpF[1024 * 512];
__device__ __align__(128) float g_WqF[1024 * 512];
__device__ __align__(128) float g_WgU[1024 * 512];
__device__ __align__(128) float g_WgC[1024 * 512];
__device__ __align__(128) float g_v_t [1024 * 32];      // v transposed [h][b]
__device__ __align__(128) float g_z1p [4 * 1024 * 32];  // z1 partials [c][row][b]
__device__ __align__(128) float g_ghp [4 * 3072 * 32];  // gh partials [c][row][b]
__device__ __align__(128) float g_gip [4 * 3072 * 32];  // gi partials [c][row][b]
__device__ __align__(128) float g_cu_tp[2 * 512 * 32];  // context partials [qh][k][b]
__device__ __align__(128) float g_ch_t[1024 * 32];      // gated context [h][b]
__device__ __align__(128) float g_s   [32 * 256];
__device__ unsigned g_barcnt;   // wraps back to 0 after each barrier (replay-safe)
__device__ unsigned g_sense;    // toggles; even #toggles per run -> replay-safe

// ---------------- scalar helpers ----------------
__device__ __forceinline__ float fexp2(float x) {
    float y; asm("ex2.approx.f32 %0, %1;" : "=f"(y) : "f"(x)); return y;
}
__device__ __forceinline__ float frcp(float x) {
    float y; asm("rcp.approx.f32 %0, %1;" : "=f"(y) : "f"(x)); return y;
}
__device__ __forceinline__ float tanh_fast(float x) {      // ~1e-6, 2 MUFU (GRU)
    return fmaf(-2.0f, frcp(1.0f + fexp2(x * TANH2L)), 1.0f);
}
__device__ __forceinline__ float tanh_hw(float x) {        // 1 MUFU (scores)
    float y; asm("tanh.approx.f32 %0, %1;" : "=f"(y) : "f"(x)); return y;
}
__device__ __forceinline__ float sigm_fast(float x) {
    return frcp(1.0f + fexp2(-x * LOG2E));
}
__device__ __forceinline__ float wsum(float v) {
    v += __shfl_xor_sync(0xffffffffu, v, 16);
    v += __shfl_xor_sync(0xffffffffu, v, 8);
    v += __shfl_xor_sync(0xffffffffu, v, 4);
    v += __shfl_xor_sync(0xffffffffu, v, 2);
    v += __shfl_xor_sync(0xffffffffu, v, 1);
    return v;
}
__device__ __forceinline__ float wmax(float v) {
    v = fmaxf(v, __shfl_xor_sync(0xffffffffu, v, 16));
    v = fmaxf(v, __shfl_xor_sync(0xffffffffu, v, 8));
    v = fmaxf(v, __shfl_xor_sync(0xffffffffu, v, 4));
    v = fmaxf(v, __shfl_xor_sync(0xffffffffu, v, 2));
    v = fmaxf(v, __shfl_xor_sync(0xffffffffu, v, 1));
    return v;
}
__device__ __forceinline__ ull ffma2(ull a, ull b, ull c) {
    ull d; asm("fma.rn.f32x2 %0, %1, %2, %3;" : "=l"(d) : "l"(a), "l"(b), "l"(c));
    return d;
}

// sense-reversing grid barrier; all state returns to initial value each run.
__device__ __forceinline__ void gsync(unsigned& sense) {
    __syncthreads();
    if (threadIdx.x == 0) {
        unsigned ns = sense ^ 1u;
        __threadfence();
        unsigned old = atomicInc(&g_barcnt, NBLK - 1);   // wraps to 0 automatically
        if (old == NBLK - 1) {
            asm volatile("st.release.gpu.u32 [%0], %1;" :: "l"(&g_sense), "r"(ns) : "memory");
        } else {
            unsigned v;
            do {
                asm volatile("ld.acquire.gpu.u32 %0, [%1];" : "=r"(v) : "l"(&g_sense));
            } while (v != ns);
        }
        __threadfence();
    }
    __syncthreads();
    sense ^= 1u;
}

// ---------------- init ----------------
__global__ void init_kernel(const float* __restrict__ v0) {
    int i = blockIdx.x * blockDim.x + threadIdx.x;
    if (i == 0) { g_barcnt = 0u; g_sense = 0u; }
    if (i < 32 * 1024) {
        int h = i >> 5, b = i & 31;
        g_v_t[i] = v0[b * 1024 + h];
    }
}

// ---------------- weight folding ----------------
__global__ void fold_kernel(const float* __restrict__ Wp,
                            const float* __restrict__ Wq,
                            const float* __restrict__ Wg) {
    int idx = blockIdx.x * blockDim.x + threadIdx.x;
    if (idx >= 1024 * 512) return;
    int h = idx >> 9, i = idx & 511;
    g_WpF[idx] = Wp[h * 1024 + i] + Wp[h * 1024 + 512 + i];
    g_WqF[idx] = Wq[h * 1024 + i] + Wq[h * 1024 + 512 + i];
    const float* wgr = Wg + (size_t)(1024 + h) * 2048;
    g_WgU[idx] = wgr[i]        + wgr[512 + i];
    g_WgC[idx] = wgr[1024 + i] + wgr[1536 + i];
}

// ---------------- precompute GEMMs: O[r,h] = sum_k A[r,k]*W[h,k] ----------------
__global__ __launch_bounds__(256) void gemm_kernel(const float* __restrict__ up,
                                                   const float* __restrict__ uq) {
    __shared__ float As[16][68];
    __shared__ float Ws[16][68];
    const int z = blockIdx.z;
    const float* A = (z == 0) ? uq : up;
    const float* W = (z == 0) ? g_WqF : ((z == 1) ? g_WpF : g_WgU);
    float*       O = (z == 0) ? g_WUq : ((z == 1) ? g_WUp : g_UG);
    const int m0 = blockIdx.y * 64;
    const int n0 = blockIdx.x * 64;
    const int tid = threadIdx.x;
    const int tr = tid >> 4;
    const int tc = tid & 15;
    const int lr = tid >> 2;
    const int lk = (tid & 3) * 4;

    float acc[4][4];
#pragma unroll
    for (int i = 0; i < 4; i++)
#pragma unroll
        for (int j = 0; j < 4; j++) acc[i][j] = 0.f;

    for (int kt = 0; kt < 512; kt += 16) {
        float4 av = *(const float4*)&A[(size_t)(m0 + lr) * 512 + kt + lk];
        float4 wv = *(const float4*)&W[(size_t)(n0 + lr) * 512 + kt + lk];
        __syncthreads();
        As[lk + 0][lr] = av.x; As[lk + 1][lr] = av.y; As[lk + 2][lr] = av.z; As[lk + 3][lr] = av.w;
        Ws[lk + 0][lr] = wv.x; Ws[lk + 1][lr] = wv.y; Ws[lk + 2][lr] = wv.z; Ws[lk + 3][lr] = wv.w;
        __syncthreads();
#pragma unroll
        for (int kk = 0; kk < 16; kk++) {
            float4 a4 = *(const float4*)&As[kk][tr * 4];
            float4 w4 = *(const float4*)&Ws[kk][tc * 4];
            float a[4] = {a4.x, a4.y, a4.z, a4.w};
            float w[4] = {w4.x, w4.y, w4.z, w4.w};
#pragma unroll
            for (int i = 0; i < 4; i++)
#pragma unroll
                for (int j = 0; j < 4; j++) acc[i][j] = fmaf(a[i], w[j], acc[i][j]);
        }
    }
#pragma unroll
    for (int i = 0; i < 4; i++) {
        float4 o = make_float4(acc[i][0], acc[i][1], acc[i][2], acc[i][3]);
        *(float4*)&O[(size_t)(m0 + tr * 4 + i) * 1024 + n0 + tc * 4] = o;
    }
}

// lane=row matvec tile: 32 rows x 32 b over a 256-k chunk.
// x staged in smem as float [k*36 + b]; acc = 16 f32x2 pairs over b.
__device__ __forceinline__ void tile_matvec(const float* __restrict__ Wrow,
                                            const float* __restrict__ shf,
                                            int k0, ull* acc) {
#pragma unroll
    for (int j = 0; j < 16; j++) acc[j] = 0ull;
#pragma unroll 1
    for (int k4 = k0; k4 < k0 + 256; k4 += 4) {
        float4 w4 = __ldg((const float4*)&Wrow[k4]);
        const float wv4[4] = {w4.x, w4.y, w4.z, w4.w};
#pragma unroll
        for (int kk = 0; kk < 4; kk++) {
            ull ww; asm("mov.b64 %0, {%1, %1};" : "=l"(ww) : "f"(wv4[kk]));
            const ulonglong2* xb = (const ulonglong2*)&shf[(k4 + kk) * 36];
#pragma unroll
            for (int j2 = 0; j2 < 8; j2++) {
                ulonglong2 xx = xb[j2];               // uniform LDS.128, 16B aligned
                acc[2 * j2]     = ffma2(xx.x, ww, acc[2 * j2]);
                acc[2 * j2 + 1] = ffma2(xx.y, ww, acc[2 * j2 + 1]);
            }
        }
    }
}

// ---------------- persistent recurrent loop ----------------
// dynamic smem: 1024*36 floats = 147456 bytes (A/D staging); aliased for B/C3.
__global__ __launch_bounds__(NTH, 1) void loop_kernel(
    const float* __restrict__ uq,
    const float* __restrict__ Vvec,
    const float* __restrict__ Wv,
    const float* __restrict__ W_hh,
    const float* __restrict__ b_hh,
    const float* __restrict__ W_ih,
    const float* __restrict__ b_ih,
    float* __restrict__ out)
{
    extern __shared__ __align__(16) float shf[];
    float2* sh2 = (float2*)shf;
    ull*    sh64 = (ull*)shf;
    const int tid  = threadIdx.x;
    const int lane = tid & 31;
    const int warp = tid >> 5;
    unsigned sense = 0u;

    for (int p = 0; p < 256; ++p) {
        // ===== Phase A: z1 = v@Wv^T (K-chunks of 256) ; gh = v@W_hh^T =====
        for (int i = tid; i < 8192; i += NTH) {           // stage v: [k][36] layout
            int k = i >> 3, bq = (i & 7) << 2;
            float4 x = __ldcg((const float4*)&g_v_t[k * 32 + bq]);
            *(float4*)&shf[k * 36 + bq] = x;
        }
        __syncthreads();
        {
            int T = warp * 140 + blockIdx.x;              // 512 tasks
            if (T < 512) {
                int g = T >> 2, c = T & 3;
                int row = g * 32 + lane;
                const float* Wrow = (g < 32)
                    ? (Wv + (size_t)row * 1024)
                    : (W_hh + (size_t)(row - 1024) * 1024);
                ull acc[16];
                tile_matvec(Wrow, shf, c * 256, acc);
                ull* dst = (g < 32)
                    ? (ull*)(g_z1p + (size_t)c * 32768 + (size_t)row * 32)
                    : (ull*)(g_ghp + (size_t)c * 98304 + (size_t)(row - 1024) * 32);
#pragma unroll
                for (int j = 0; j < 16; j++) dst[j] = acc[j];
            }
        }
        gsync(sense);

        // ===== Phase B: per-b blocks; s[b,q] = sum_h tanh(...)*Vvec =====
        if (blockIdx.x < 128) {
            int b = blockIdx.x >> 2, qq = blockIdx.x & 3;
            for (int h = tid; h < 1024; h += NTH) {
                float z = __ldg(&g_WUp[((size_t)p * 32 + b) * 1024 + h]);
#pragma unroll
                for (int c = 0; c < 4; c++)
                    z += __ldcg(&g_z1p[c * 32768 + h * 32 + b]);
                shf[h] = z;
            }
            __syncthreads();
            const float* vv = Vvec + b * 1024;
#pragma unroll 1
            for (int qi = 0; qi < 4; qi++) {
                int q = qq * 64 + warp * 4 + qi;
                const float* wuq = g_WUq + ((size_t)q * 32 + b) * 1024;
                float part = 0.f;
#pragma unroll
                for (int h = lane * 4; h < 1024; h += 128) {
                    float4 a = __ldg((const float4*)(wuq + h));
                    float4 z = *(const float4*)(shf + h);
                    float4 u = __ldg((const float4*)(vv + h));
                    part = fmaf(tanh_hw(a.x + z.x), u.x, part);
                    part = fmaf(tanh_hw(a.y + z.y), u.y, part);
                    part = fmaf(tanh_hw(a.z + z.z), u.z, part);
                    part = fmaf(tanh_hw(a.w + z.w), u.w, part);
                }
                part = wsum(part);
                if (lane == 0) g_s[b * 256 + q] = part;
            }
        }
        gsync(sense);

        // ===== Phase C2: softmax (recomputed) + context partials -> [qh][k][b]
        {
            int t = blockIdx.x * 2 + warp;
            if (warp < 2 && t < 256) {
                int b = t >> 3, r3 = t & 7;
                int jb = ((r3 >> 1) & 3) * 128;
                int qh = r3 & 1;
                float sv[8]; float mx = -3.4e38f;
#pragma unroll
                for (int i = 0; i < 8; i++) {
                    sv[i] = __ldcg(&g_s[b * 256 + i * 32 + lane]);
                    mx = fmaxf(mx, sv[i]);
                }
                mx = wmax(mx);
                float zsum = 0.f;
#pragma unroll
                for (int i = 0; i < 8; i++) { sv[i] = fexp2((sv[i] - mx) * LOG2E); zsum += sv[i]; }
                zsum = wsum(zsum);
                float inv = frcp(zsum);
#pragma unroll
                for (int i = 0; i < 8; i++) sv[i] *= inv;
                float4 acc = make_float4(0.f, 0.f, 0.f, 0.f);
                const int q0 = qh * 128;
#pragma unroll 4
                for (int q = q0; q < q0 + 128; ++q) {
                    float aq = __shfl_sync(0xffffffffu, sv[q >> 5], q & 31);
                    float4 u = __ldg((const float4*)&uq[(size_t)(q * 32 + b) * 512 + jb + lane * 4]);
                    acc.x = fmaf(aq, u.x, acc.x); acc.y = fmaf(aq, u.y, acc.y);
                    acc.z = fmaf(aq, u.z, acc.z); acc.w = fmaf(aq, u.w, acc.w);
                }
                float* dst = g_cu_tp + qh * 16384;
                int hb = jb + lane * 4;
                dst[(hb + 0) * 32 + b] = acc.x;
                dst[(hb + 1) * 32 + b] = acc.y;
                dst[(hb + 2) * 32 + b] = acc.z;
                dst[(hb + 3) * 32 + b] = acc.w;
            }
        }
        gsync(sense);

        // ===== Phase C3: ch[b,h] = sigmoid(UG + cu@WgC^T) * cu[b,h&511] =====
        for (int i = tid; i < 8192; i += NTH) {           // stage cu: k-pairs [k2*33+b]
            int b = i & 31, k2 = i >> 5;
            float x0 = __ldcg(&g_cu_tp[(2 * k2) * 32 + b])
                     + __ldcg(&g_cu_tp[16384 + (2 * k2) * 32 + b]);
            float x1 = __ldcg(&g_cu_tp[(2 * k2 + 1) * 32 + b])
                     + __ldcg(&g_cu_tp[16384 + (2 * k2 + 1) * 32 + b]);
            sh2[k2 * 33 + b] = make_float2(x0, x1);
        }
        __syncthreads();
        {
            int h = blockIdx.x * 8 + warp;
            if (warp < 8 && h < 1024) {
                const float* wg = g_WgC + (size_t)h * 512;
                ull aA = 0, aB = 0;
#pragma unroll 2
                for (int k2 = 0; k2 < 256; k2 += 2) {
                    ull s01 = sh64[k2 * 33 + lane];
                    ull s23 = sh64[(k2 + 1) * 33 + lane];
                    ulonglong2 w = *(const ulonglong2*)(wg + k2 * 2);
                    aA = ffma2(w.x, s01, aA);
                    aB = ffma2(w.y, s23, aB);
                }
                float2 fa, fb;
                asm("mov.b64 {%0, %1}, %2;" : "=f"(fa.x), "=f"(fa.y) : "l"(aA));
                asm("mov.b64 {%0, %1}, %2;" : "=f"(fb.x), "=f"(fb.y) : "l"(aB));
                float acc = (fa.x + fb.x) + (fa.y + fb.y)
                          + __ldg(&g_UG[((size_t)p * 32 + lane) * 1024 + h]);
                float2 cv2 = sh2[((h & 511) >> 1) * 33 + lane];
                float cval = (h & 1) ? cv2.y : cv2.x;
                g_ch_t[h * 32 + lane] = sigm_fast(acc) * cval;
            }
        }
        gsync(sense);

        // ===== Phase D: gi partials = ch@W_ih^T (K-chunks of 256) =====
        for (int i = tid; i < 8192; i += NTH) {           // stage ch: [k][36]
            int k = i >> 3, bq = (i & 7) << 2;
            float4 x = __ldcg((const float4*)&g_ch_t[k * 32 + bq]);
            *(float4*)&shf[k * 36 + bq] = x;
        }
        __syncthreads();
        {
            int T = warp * 140 + blockIdx.x;              // 384 tasks
            if (T < 384) {
                int g = T >> 2, c = T & 3;
                int row = g * 32 + lane;                  // 0..3071
                ull acc[16];
                tile_matvec(W_ih + (size_t)row * 1024, shf, c * 256, acc);
                ull* dst = (ull*)(g_gip + (size_t)c * 98304 + (size_t)row * 32);
#pragma unroll
                for (int j = 0; j < 16; j++) dst[j] = acc[j];
            }
        }
        gsync(sense);

        // ===== Phase E: GRU combine, update v_t, emit output =====
        {
            int idx = blockIdx.x * NTH + tid;
            if (idx < 32768) {
                int h = idx >> 5, b = idx & 31;
                float gr = 0.f, gz = 0.f, gn = 0.f, hr = 0.f, hz = 0.f, hn = 0.f;
#pragma unroll
                for (int c = 0; c < 4; c++) {
                    gr += __ldcg(&g_gip[c * 98304 + h * 32 + b]);
                    gz += __ldcg(&g_gip[c * 98304 + (1024 + h) * 32 + b]);
                    gn += __ldcg(&g_gip[c * 98304 + (2048 + h) * 32 + b]);
                    hr += __ldcg(&g_ghp[c * 98304 + h * 32 + b]);
                    hz += __ldcg(&g_ghp[c * 98304 + (1024 + h) * 32 + b]);
                    hn += __ldcg(&g_ghp[c * 98304 + (2048 + h) * 32 + b]);
                }
                gr += __ldg(&b_ih[h]);          hr += __ldg(&b_hh[h]);
                gz += __ldg(&b_ih[1024 + h]);   hz += __ldg(&b_hh[1024 + h]);
                gn += __ldg(&b_ih[2048 + h]);   hn += __ldg(&b_hh[2048 + h]);
                float vold = __ldcg(&g_v_t[h * 32 + b]);
                float r  = sigm_fast(gr + hr);
                float zg = sigm_fast(gz + hz);
                float n  = tanh_fast(fmaf(r, hn, gn));
                float vn = fmaf(zg, vold - n, n);
                g_v_t[h * 32 + b] = vn;
                out[((size_t)p * 32 + b) * 1024 + h] = vn;
            }
        }
        gsync(sense);
    }
}

// ---------------- launch ----------------
extern "C" void kernel_launch(void* const* d_in, const int* in_sizes, int n_in,
                              void* d_out, int out_size) {
    const float* up   = (const float*)d_in[0];
    const float* uq   = (const float*)d_in[1];
    const float* v0   = (const float*)d_in[2];
    const float* Vvec = (const float*)d_in[3];
    const float* Wp   = (const float*)d_in[4];
    const float* Wq   = (const float*)d_in[5];
    const float* Wv   = (const float*)d_in[6];
    const float* Wg   = (const float*)d_in[7];
    const float* W_ih = (const float*)d_in[8];
    const float* W_hh = (const float*)d_in[9];
    const float* b_ih = (const float*)d_in[10];
    const float* b_hh = (const float*)d_in[11];
    float* out = (float*)d_out;

    const int smem_bytes = 1024 * 36 * (int)sizeof(float);   // 147456
    cudaFuncSetAttribute(loop_kernel, cudaFuncAttributeMaxDynamicSharedMemorySize,
                         smem_bytes);

    init_kernel<<<64, 512>>>(v0);
    fold_kernel<<<2048, 256>>>(Wp, Wq, Wg);
    dim3 gg(16, 128, 3);
    gemm_kernel<<<gg, 256>>>(up, uq);
    loop_kernel<<<NBLK, NTH, smem_bytes>>>(uq, Vvec, Wv, W_hh, b_hh,
                                           W_ih, b_ih, out);
}

// round 15
// speedup vs baseline: 1.5717x; 1.2186x over previous
#include <cuda_runtime.h>
#include <cuda_bf16.h>

// ---------------- problem constants ----------------
#define NBLK   140
#define NTH    512
#define LOG2E  1.4426950408889634f
#define TANH2L 2.8853900817779268f   // 2*log2(e)

typedef unsigned long long ull;

// smem float-offsets
#define XS_OFF   0                  // 32768 floats staging (A/D); aliased by B/C
#define PART_OFF 32768              // 16*1088 = 17408 floats partials
#define SMEM_FLOATS (32768 + 17408) // 50176 -> 200704 bytes

// C-phase offsets (alias XS region)
#define C_S_OFF    0      // 256 scores
#define C_STAT_OFF 256    // 2 stats
#define C_CU_OFF   512    // 512 cu
#define C_RED_OFF  1024   // 16*513 = 8208 partials

// ---------------- device scratch (allocs forbidden) ----------------
__device__ __align__(128) float g_WUp[8192 * 1024];  // [p*32+b][h]
__device__ __align__(128) float g_WUq[8192 * 1024];  // [q*32+b][h]
__device__ __align__(128) float g_UG [8192 * 1024];  // [p*32+b][h]
__device__ __align__(128) float g_WpF[1024 * 512];
__device__ __align__(128) float g_WqF[1024 * 512];
__device__ __align__(128) float g_WgU[1024 * 512];
__device__ __align__(128) float g_WgC[1024 * 512];
__device__ __align__(128) float g_v_t [1024 * 32];   // v      [h][b]
__device__ __align__(128) float g_z1  [32 * 1024];   // z1     [b][h]
__device__ __align__(128) float g_gh_t[3072 * 32];   // gh     [row][b]
__device__ __align__(128) float g_gi_t[3072 * 32];   // gi     [row][b]
__device__ __align__(128) float g_ch_t[1024 * 32];   // gated context [h][b]
__device__ __align__(128) float g_s   [32 * 256];
__device__ unsigned g_barcnt;   // wraps to 0 at each barrier (replay-safe)
__device__ unsigned g_sense;    // toggles; even count per run -> replay-safe

// ---------------- scalar helpers ----------------
__device__ __forceinline__ float fexp2(float x) {
    float y; asm("ex2.approx.f32 %0, %1;" : "=f"(y) : "f"(x)); return y;
}
__device__ __forceinline__ float frcp(float x) {
    float y; asm("rcp.approx.f32 %0, %1;" : "=f"(y) : "f"(x)); return y;
}
__device__ __forceinline__ float tanh_fast(float x) {      // ~1e-6, 2 MUFU (GRU)
    return fmaf(-2.0f, frcp(1.0f + fexp2(x * TANH2L)), 1.0f);
}
__device__ __forceinline__ float tanh_hw(float x) {        // 1 MUFU (scores)
    float y; asm("tanh.approx.f32 %0, %1;" : "=f"(y) : "f"(x)); return y;
}
__device__ __forceinline__ float sigm_fast(float x) {
    return frcp(1.0f + fexp2(-x * LOG2E));
}
__device__ __forceinline__ float wsum(float v) {
    v += __shfl_xor_sync(0xffffffffu, v, 16);
    v += __shfl_xor_sync(0xffffffffu, v, 8);
    v += __shfl_xor_sync(0xffffffffu, v, 4);
    v += __shfl_xor_sync(0xffffffffu, v, 2);
    v += __shfl_xor_sync(0xffffffffu, v, 1);
    return v;
}
__device__ __forceinline__ float wmax(float v) {
    v = fmaxf(v, __shfl_xor_sync(0xffffffffu, v, 16));
    v = fmaxf(v, __shfl_xor_sync(0xffffffffu, v, 8));
    v = fmaxf(v, __shfl_xor_sync(0xffffffffu, v, 4));
    v = fmaxf(v, __shfl_xor_sync(0xffffffffu, v, 2));
    v = fmaxf(v, __shfl_xor_sync(0xffffffffu, v, 1));
    return v;
}
__device__ __forceinline__ ull ffma2(ull a, ull b, ull c) {
    ull d; asm("fma.rn.f32x2 %0, %1, %2, %3;" : "=l"(d) : "l"(a), "l"(b), "l"(c));
    return d;
}

// sense-reversing grid barrier; all state returns to initial value each run.
__device__ __forceinline__ void gsync(unsigned& sense) {
    __syncthreads();
    if (threadIdx.x == 0) {
        unsigned ns = sense ^ 1u;
        __threadfence();
        unsigned old = atomicInc(&g_barcnt, NBLK - 1);   // wraps to 0
        if (old == NBLK - 1) {
            asm volatile("st.release.gpu.u32 [%0], %1;" :: "l"(&g_sense), "r"(ns) : "memory");
        } else {
            unsigned v;
            while (true) {
                asm volatile("ld.acquire.gpu.u32 %0, [%1];" : "=r"(v) : "l"(&g_sense));
                if (v == ns) break;
                __nanosleep(32);
            }
        }
        __threadfence();
    }
    __syncthreads();
    sense ^= 1u;
}

// ---------------- init ----------------
__global__ void init_kernel(const float* __restrict__ v0) {
    int i = blockIdx.x * blockDim.x + threadIdx.x;
    if (i == 0) { g_barcnt = 0u; g_sense = 0u; }
    if (i < 32 * 1024) {
        int h = i >> 5, b = i & 31;
        g_v_t[i] = v0[b * 1024 + h];
    }
}

// ---------------- weight folding ----------------
__global__ void fold_kernel(const float* __restrict__ Wp,
                            const float* __restrict__ Wq,
                            const float* __restrict__ Wg) {
    int idx = blockIdx.x * blockDim.x + threadIdx.x;
    if (idx >= 1024 * 512) return;
    int h = idx >> 9, i = idx & 511;
    g_WpF[idx] = Wp[h * 1024 + i] + Wp[h * 1024 + 512 + i];
    g_WqF[idx] = Wq[h * 1024 + i] + Wq[h * 1024 + 512 + i];
    const float* wgr = Wg + (size_t)(1024 + h) * 2048;
    g_WgU[idx] = wgr[i]        + wgr[512 + i];
    g_WgC[idx] = wgr[1024 + i] + wgr[1536 + i];
}

// ---------------- precompute GEMMs: O[r,h] = sum_k A[r,k]*W[h,k] ----------------
__global__ __launch_bounds__(256) void gemm_kernel(const float* __restrict__ up,
                                                   const float* __restrict__ uq) {
    __shared__ float As[16][68];
    __shared__ float Ws[16][68];
    const int z = blockIdx.z;
    const float* A = (z == 0) ? uq : up;
    const float* W = (z == 0) ? g_WqF : ((z == 1) ? g_WpF : g_WgU);
    float*       O = (z == 0) ? g_WUq : ((z == 1) ? g_WUp : g_UG);
    const int m0 = blockIdx.y * 64;
    const int n0 = blockIdx.x * 64;
    const int tid = threadIdx.x;
    const int tr = tid >> 4;
    const int tc = tid & 15;
    const int lr = tid >> 2;
    const int lk = (tid & 3) * 4;

    float acc[4][4];
#pragma unroll
    for (int i = 0; i < 4; i++)
#pragma unroll
        for (int j = 0; j < 4; j++) acc[i][j] = 0.f;

    for (int kt = 0; kt < 512; kt += 16) {
        float4 av = *(const float4*)&A[(size_t)(m0 + lr) * 512 + kt + lk];
        float4 wv = *(const float4*)&W[(size_t)(n0 + lr) * 512 + kt + lk];
        __syncthreads();
        As[lk + 0][lr] = av.x; As[lk + 1][lr] = av.y; As[lk + 2][lr] = av.z; As[lk + 3][lr] = av.w;
        Ws[lk + 0][lr] = wv.x; Ws[lk + 1][lr] = wv.y; Ws[lk + 2][lr] = wv.z; Ws[lk + 3][lr] = wv.w;
        __syncthreads();
#pragma unroll
        for (int kk = 0; kk < 16; kk++) {
            float4 a4 = *(const float4*)&As[kk][tr * 4];
            float4 w4 = *(const float4*)&Ws[kk][tc * 4];
            float a[4] = {a4.x, a4.y, a4.z, a4.w};
            float w[4] = {w4.x, w4.y, w4.z, w4.w};
#pragma unroll
            for (int i = 0; i < 4; i++)
#pragma unroll
                for (int j = 0; j < 4; j++) acc[i][j] = fmaf(a[i], w[j], acc[i][j]);
        }
    }
#pragma unroll
    for (int i = 0; i < 4; i++) {
        float4 o = make_float4(acc[i][0], acc[i][1], acc[i][2], acc[i][3]);
        *(float4*)&O[(size_t)(m0 + tr * 4 + i) * 1024 + n0 + tc * 4] = o;
    }
}

// lane=row tile: 32 rows x 32 b over a 64-k chunk; x staged flat [k*32 + b].
__device__ __forceinline__ void tile_mv64(const float* __restrict__ Wrow,
                                          const float* __restrict__ xs,
                                          int k0, ull* acc) {
#pragma unroll
    for (int j = 0; j < 16; j++) acc[j] = 0ull;
#pragma unroll 4
    for (int k4 = k0; k4 < k0 + 64; k4 += 4) {
        float4 w4 = __ldg((const float4*)&Wrow[k4]);
        float wv[4] = {w4.x, w4.y, w4.z, w4.w};
#pragma unroll
        for (int kk = 0; kk < 4; kk++) {
            ull ww; asm("mov.b64 %0, {%1, %1};" : "=l"(ww) : "f"(wv[kk]));
            const ulonglong2* xb = (const ulonglong2*)&xs[(k4 + kk) * 32];
#pragma unroll
            for (int j2 = 0; j2 < 8; j2++) {
                ulonglong2 xx = xb[j2];              // uniform LDS.128 broadcast
                acc[2 * j2]     = ffma2(xx.x, ww, acc[2 * j2]);
                acc[2 * j2 + 1] = ffma2(xx.y, ww, acc[2 * j2 + 1]);
            }
        }
    }
}

// ---------------- persistent recurrent loop ----------------
__global__ __launch_bounds__(NTH, 1) void loop_kernel(
    const float* __restrict__ uq,
    const float* __restrict__ Vvec,
    const float* __restrict__ Wv,
    const float* __restrict__ W_hh,
    const float* __restrict__ b_hh,
    const float* __restrict__ W_ih,
    const float* __restrict__ b_ih,
    float* __restrict__ out)
{
    extern __shared__ __align__(16) float sp[];
    const int tid  = threadIdx.x;
    const int lane = tid & 31;
    const int warp = tid >> 5;
    const int bid  = blockIdx.x;
    unsigned sense = 0u;

    for (int p = 0; p < 256; ++p) {
        // ===== Phase A: z1 = v@Wv^T ; gh = v@W_hh^T (in-block K-split x16) =====
        if (bid < 128) {
            // stage v [k*32+b] (131 KB), coalesced float4 from g_v_t
            for (int i = tid; i < 8192; i += NTH)
                *(float4*)&sp[XS_OFF + i * 4] = __ldcg((const float4*)&g_v_t[i * 4]);
            __syncthreads();
            const int g = bid;
            const float* Wrow = (g < 32)
                ? (Wv   + (size_t)(g * 32 + lane) * 1024)
                : (W_hh + (size_t)((g - 32) * 32 + lane) * 1024);
            ull acc[16];
            tile_mv64(Wrow, sp + XS_OFF, warp * 64, acc);
            ull* pp = (ull*)&sp[PART_OFF + warp * 1088 + lane * 34];
#pragma unroll
            for (int j = 0; j < 16; j++) pp[j] = acc[j];
            __syncthreads();
            if (g < 32) {
                // reduce + write z1 as [b][h]
                for (int e = tid; e < 1024; e += NTH) {
                    int b = e >> 5, hl = e & 31;
                    float s = 0.f;
#pragma unroll
                    for (int w = 0; w < 16; w++)
                        s += sp[PART_OFF + w * 1088 + hl * 34 + b];
                    g_z1[b * 1024 + g * 32 + hl] = s;
                }
            } else {
                // reduce + write gh as [row][b]
                for (int e = tid; e < 1024; e += NTH) {
                    int b = e & 31, hl = e >> 5;
                    float s = 0.f;
#pragma unroll
                    for (int w = 0; w < 16; w++)
                        s += sp[PART_OFF + w * 1088 + hl * 34 + b];
                    g_gh_t[((g - 32) * 32 + hl) * 32 + b] = s;
                }
            }
        }
        gsync(sense);

        // ===== Phase B: s[b,q] = sum_h tanh(WUq + WUp[p]+z1) * Vvec =====
        if (bid < 128) {
            int b = bid >> 2, qq = bid & 3;
            for (int h = tid; h < 1024; h += NTH)
                sp[XS_OFF + h] = __ldg(&g_WUp[((size_t)p * 32 + b) * 1024 + h])
                               + __ldcg(&g_z1[b * 1024 + h]);
            __syncthreads();
            const float* vv = Vvec + b * 1024;
#pragma unroll 1
            for (int qi = 0; qi < 4; qi++) {
                int q = qq * 64 + warp * 4 + qi;
                const float* wuq = g_WUq + ((size_t)q * 32 + b) * 1024;
                float part = 0.f;
#pragma unroll
                for (int h = lane * 4; h < 1024; h += 128) {
                    float4 a = __ldg((const float4*)(wuq + h));
                    float4 z = *(const float4*)(sp + XS_OFF + h);
                    float4 u = __ldg((const float4*)(vv + h));
                    part = fmaf(tanh_hw(a.x + z.x), u.x, part);
                    part = fmaf(tanh_hw(a.y + z.y), u.y, part);
                    part = fmaf(tanh_hw(a.z + z.z), u.z, part);
                    part = fmaf(tanh_hw(a.w + z.w), u.w, part);
                }
                part = wsum(part);
                if (lane == 0) g_s[b * 256 + q] = part;
            }
        }
        gsync(sense);

        // ===== Phase C (fused): softmax + context + gate, one block per b =====
        if (bid < 32) {
            const int b = bid;
            if (tid < 256) sp[C_S_OFF + tid] = __ldcg(&g_s[b * 256 + tid]);
            __syncthreads();
            if (warp == 0) {
                float sv[8], mx = -3.4e38f;
#pragma unroll
                for (int i = 0; i < 8; i++) {
                    sv[i] = sp[C_S_OFF + i * 32 + lane];
                    mx = fmaxf(mx, sv[i]);
                }
                mx = wmax(mx);
                float zs = 0.f;
#pragma unroll
                for (int i = 0; i < 8; i++) zs += fexp2((sv[i] - mx) * LOG2E);
                zs = wsum(zs);
                if (lane == 0) { sp[C_STAT_OFF] = mx; sp[C_STAT_OFF + 1] = frcp(zs); }
            }
            __syncthreads();
            const float mx = sp[C_STAT_OFF], inv = sp[C_STAT_OFF + 1];
            // context: warp w handles q = w*16 .. w*16+15; lane owns 16 cols
            float4 acc[4];
#pragma unroll
            for (int i = 0; i < 4; i++) acc[i] = make_float4(0.f, 0.f, 0.f, 0.f);
#pragma unroll 2
            for (int qi = 0; qi < 16; qi++) {
                int q = warp * 16 + qi;
                float aq = fexp2((sp[C_S_OFF + q] - mx) * LOG2E) * inv;
                const float4* uqp = (const float4*)&uq[((size_t)q * 32 + b) * 512];
#pragma unroll
                for (int i = 0; i < 4; i++) {
                    float4 u = __ldg(&uqp[i * 32 + lane]);
                    acc[i].x = fmaf(aq, u.x, acc[i].x);
                    acc[i].y = fmaf(aq, u.y, acc[i].y);
                    acc[i].z = fmaf(aq, u.z, acc[i].z);
                    acc[i].w = fmaf(aq, u.w, acc[i].w);
                }
            }
#pragma unroll
            for (int i = 0; i < 4; i++) {
                int base = C_RED_OFF + warp * 513 + i * 128 + lane * 4;
                sp[base + 0] = acc[i].x; sp[base + 1] = acc[i].y;
                sp[base + 2] = acc[i].z; sp[base + 3] = acc[i].w;
            }
            __syncthreads();
            if (tid < 512) {
                float s = 0.f;
#pragma unroll
                for (int w = 0; w < 16; w++) s += sp[C_RED_OFF + w * 513 + tid];
                sp[C_CU_OFF + tid] = s;
            }
            __syncthreads();
            // gate: 16 warps x 64 rows, 4-row interleave
            for (int r0 = warp * 4; r0 < 1024; r0 += 64) {
                float part0 = 0.f, part1 = 0.f, part2 = 0.f, part3 = 0.f;
#pragma unroll
                for (int i = 0; i < 4; i++) {
                    float4 c4 = *(const float4*)&sp[C_CU_OFF + i * 128 + lane * 4];
                    float4 w0 = __ldg((const float4*)&g_WgC[(size_t)(r0 + 0) * 512 + i * 128 + lane * 4]);
                    float4 w1 = __ldg((const float4*)&g_WgC[(size_t)(r0 + 1) * 512 + i * 128 + lane * 4]);
                    float4 w2 = __ldg((const float4*)&g_WgC[(size_t)(r0 + 2) * 512 + i * 128 + lane * 4]);
                    float4 w3 = __ldg((const float4*)&g_WgC[(size_t)(r0 + 3) * 512 + i * 128 + lane * 4]);
                    part0 += w0.x * c4.x + w0.y * c4.y + w0.z * c4.z + w0.w * c4.w;
                    part1 += w1.x * c4.x + w1.y * c4.y + w1.z * c4.z + w1.w * c4.w;
                    part2 += w2.x * c4.x + w2.y * c4.y + w2.z * c4.z + w2.w * c4.w;
                    part3 += w3.x * c4.x + w3.y * c4.y + w3.z * c4.z + w3.w * c4.w;
                }
                part0 = wsum(part0); part1 = wsum(part1);
                part2 = wsum(part2); part3 = wsum(part3);
                if (lane == 0) {
                    float pr[4] = {part0, part1, part2, part3};
#pragma unroll
                    for (int rr = 0; rr < 4; rr++) {
                        int r = r0 + rr;
                        float ug = __ldg(&g_UG[((size_t)p * 32 + b) * 1024 + r]);
                        float cv = sp[C_CU_OFF + (r & 511)];
                        g_ch_t[r * 32 + b] = sigm_fast(pr[rr] + ug) * cv;
                    }
                }
            }
        }
        gsync(sense);

        // ===== Phase D: gi = ch@W_ih^T (96 blocks, in-block K-split x16) =====
        if (bid < 96) {
            for (int i = tid; i < 8192; i += NTH)
                *(float4*)&sp[XS_OFF + i * 4] = __ldcg((const float4*)&g_ch_t[i * 4]);
            __syncthreads();
            const float* Wrow = W_ih + (size_t)(bid * 32 + lane) * 1024;
            ull acc[16];
            tile_mv64(Wrow, sp + XS_OFF, warp * 64, acc);
            ull* pp = (ull*)&sp[PART_OFF + warp * 1088 + lane * 34];
#pragma unroll
            for (int j = 0; j < 16; j++) pp[j] = acc[j];
            __syncthreads();
            for (int e = tid; e < 1024; e += NTH) {
                int b = e & 31, hl = e >> 5;
                float s = 0.f;
#pragma unroll
                for (int w = 0; w < 16; w++)
                    s += sp[PART_OFF + w * 1088 + hl * 34 + b];
                g_gi_t[(bid * 32 + hl) * 32 + b] = s;
            }
        }
        gsync(sense);

        // ===== Phase E: GRU combine (coalesced [row][b] reads) =====
        {
            int idx = bid * NTH + tid;
            if (idx < 32768) {
                int b = idx & 31, h = idx >> 5;
                float gr = __ldcg(&g_gi_t[h * 32 + b])          + __ldg(&b_ih[h]);
                float gz = __ldcg(&g_gi_t[(1024 + h) * 32 + b]) + __ldg(&b_ih[1024 + h]);
                float gn = __ldcg(&g_gi_t[(2048 + h) * 32 + b]) + __ldg(&b_ih[2048 + h]);
                float hr = __ldcg(&g_gh_t[h * 32 + b])          + __ldg(&b_hh[h]);
                float hz = __ldcg(&g_gh_t[(1024 + h) * 32 + b]) + __ldg(&b_hh[1024 + h]);
                float hn = __ldcg(&g_gh_t[(2048 + h) * 32 + b]) + __ldg(&b_hh[2048 + h]);
                float vold = __ldcg(&g_v_t[h * 32 + b]);
                float r  = sigm_fast(gr + hr);
                float zg = sigm_fast(gz + hz);
                float n  = tanh_fast(fmaf(r, hn, gn));
                float vn = fmaf(zg, vold - n, n);
                g_v_t[h * 32 + b] = vn;
                out[((size_t)p * 32 + b) * 1024 + h] = vn;
            }
        }
        gsync(sense);
    }
}

// ---------------- launch ----------------
extern "C" void kernel_launch(void* const* d_in, const int* in_sizes, int n_in,
                              void* d_out, int out_size) {
    const float* up   = (const float*)d_in[0];
    const float* uq   = (const float*)d_in[1];
    const float* v0   = (const float*)d_in[2];
    const float* Vvec = (const float*)d_in[3];
    const float* Wp   = (const float*)d_in[4];
    const float* Wq   = (const float*)d_in[5];
    const float* Wv   = (const float*)d_in[6];
    const float* Wg   = (const float*)d_in[7];
    const float* W_ih = (const float*)d_in[8];
    const float* W_hh = (const float*)d_in[9];
    const float* b_ih = (const float*)d_in[10];
    const float* b_hh = (const float*)d_in[11];
    float* out = (float*)d_out;

    const int smem_bytes = SMEM_FLOATS * (int)sizeof(float);   // 200704
    cudaFuncSetAttribute(loop_kernel, cudaFuncAttributeMaxDynamicSharedMemorySize,
                         smem_bytes);

    init_kernel<<<64, 512>>>(v0);
    fold_kernel<<<2048, 256>>>(Wp, Wq, Wg);
    dim3 gg(16, 128, 3);
    gemm_kernel<<<gg, 256>>>(up, uq);
    loop_kernel<<<NBLK, NTH, smem_bytes>>>(uq, Vvec, Wv, W_hh, b_hh,
                                           W_ih, b_ih, out);
}